// round 17
// baseline (speedup 1.0000x reference)
#include <cuda_runtime.h>
#include <cstdint>

// Input:  x (2,8,256,256) fp32, F (3,3) fp32
// Output: (2,8,256,256) fp32 epipolar line-sum.
//
// Pipeline:
//  1) transpose_k : x -> g_t4[h][w][pg] (4-plane float4 chunks)
//  2) pass1_k     : 32-element chunk sums (both directions)
//  3) pass2_k     : chunk carries + serial write of prefix tables, [t][line] layout
//  4) fused_k     : per block = 8 pixels; phase1 warp/pixel exact idx + RLE -> smem;
//                   phase2 warp/pixel gather (4 pg x 8 run-stride lanes)
//
// Table layout: tab[(t)*256 + line][pg], t in 0..256. Consecutive-run endpoints
// (t1_j, c_j) / (t1_j, c_j+-1) are adjacent 64B entries -> shared 128B lines.

#define FULLM 0xffffffffu

__device__ float4 g_t4  [256 * 256 * 4];         // 4 MB   repacked image
__device__ float4 g_tabC[257 * 256 * 4];         // 4.2MB  col prefix, [t=w][line=h]
__device__ float4 g_tabR[257 * 256 * 4];         // 4.2MB  row prefix, [t=h][line=w]
__device__ float4 g_chunk[2 * 8 * 256 * 4];      // chunk sums [dir][chunk][line][pg]

__global__ void __launch_bounds__(256) transpose_k(const float* __restrict__ in) {
    int gid = blockIdx.x * 256 + threadIdx.x;    // 262144 = 65536 px * 4 groups
    int px = gid >> 2, pg = gid & 3;
    float4 o;
    o.x = __ldg(in + (pg * 4 + 0) * 65536 + px);
    o.y = __ldg(in + (pg * 4 + 1) * 65536 + px);
    o.z = __ldg(in + (pg * 4 + 2) * 65536 + px);
    o.w = __ldg(in + (pg * 4 + 3) * 65536 + px);
    g_t4[px * 4 + pg] = o;
}

// Pass 1: thread = (dir, chunk, line, pg); sums its 32-element chunk.
__global__ void __launch_bounds__(256) pass1_k() {
    int gid  = blockIdx.x * 256 + threadIdx.x;   // < 16384
    int pg   = gid & 3;
    int line = (gid >> 2) & 255;
    int chunk= (gid >> 10) & 7;
    int dir  = gid >> 13;                        // 0 = col(line=h,t=w), 1 = row
    float4 s = make_float4(0.f, 0.f, 0.f, 0.f);
    int t0 = chunk * 32;
#pragma unroll 4
    for (int i = 0; i < 32; ++i) {
        int t = t0 + i;
        int px = dir ? (t * 256 + line) : (line * 256 + t);
        float4 x = __ldg(g_t4 + px * 4 + pg);
        s.x += x.x; s.y += x.y; s.z += x.z; s.w += x.w;
    }
    g_chunk[gid] = s;
}

// Pass 2: same mapping; carry from earlier chunks, then serial exclusive writes.
__global__ void __launch_bounds__(256) pass2_k() {
    int gid  = blockIdx.x * 256 + threadIdx.x;
    int pg   = gid & 3;
    int line = (gid >> 2) & 255;
    int chunk= (gid >> 10) & 7;
    int dir  = gid >> 13;
    float4* __restrict__ Tb = dir ? g_tabR : g_tabC;

    float4 carry = make_float4(0.f, 0.f, 0.f, 0.f);
    int cbase = (dir * 8) * 1024 + line * 4 + pg;
    for (int c = 0; c < chunk; ++c) {            // left-assoc chunk carries
        float4 s = __ldg(g_chunk + cbase + c * 1024);
        carry.x += s.x; carry.y += s.y; carry.z += s.z; carry.w += s.w;
    }
    if (chunk == 0)                              // P[t=0] = 0
        Tb[(0 * 256 + line) * 4 + pg] = make_float4(0.f, 0.f, 0.f, 0.f);

    int t0 = chunk * 32;
#pragma unroll 4
    for (int i = 0; i < 32; ++i) {
        int t = t0 + i;
        int px = dir ? (t * 256 + line) : (line * 256 + t);
        float4 x = __ldg(g_t4 + px * 4 + pg);
        carry.x += x.x; carry.y += x.y; carry.z += x.z; carry.w += x.w;
        Tb[((t + 1) * 256 + line) * 4 + pg] = carry;
    }
}

// Block = 8 consecutive-w pixels. Phase1: warp/pixel idx+RLE to smem.
// Phase2: warp/pixel gather, lanes = pg(0..3) x runstride(0..7).
__global__ void __launch_bounds__(256) fused_k(const float* __restrict__ Fm,
                                               float* __restrict__ out) {
    __shared__ unsigned s_run[8][264];
    __shared__ int      s_n[8];
    __shared__ unsigned s_mode[8];                  // 1 = col

    const int lane = threadIdx.x & 31;
    const int warp = threadIdx.x >> 5;
    const int h     = blockIdx.x >> 5;
    const int wbase = (blockIdx.x & 31) * 8;
    const int w  = wbase + warp;
    const int px = h * 256 + w;
    const float u = (float)w, v = (float)h;

    // ---- Phase 1: EXACT index arithmetic (R4..R16 — do not touch) + RLE ----
    const float F0 = __ldg(Fm+0), F1 = __ldg(Fm+1), F2 = __ldg(Fm+2);
    const float F3 = __ldg(Fm+3), F4 = __ldg(Fm+4), F5 = __ldg(Fm+5);
    const float F6 = __ldg(Fm+6), F7 = __ldg(Fm+7), F8 = __ldg(Fm+8);
    float A = __fadd_rn(__fmaf_rn(F3, v, __fmul_rn(F0, u)), F6);
    float B = __fadd_rn(__fmaf_rn(F4, v, __fmul_rn(F1, u)), F7);
    float C = __fadd_rn(__fmaf_rn(F5, v, __fmul_rn(F2, u)), F8);

    const bool col = (fabsf(B) >= fabsf(A));
    float P, Q;
    if (col) { P = A; Q = (fabsf(B) < 1e-8f) ? 1e-8f : B; }
    else     { P = B; Q = (fabsf(A) < 1e-8f) ? 1e-8f : A; }
    const float rq  = __frcp_rn(Q);
    const float nrq = -rq;

    unsigned vals[8];
    float tf = (float)(lane * 8);
#pragma unroll
    for (int j = 0; j < 8; ++j, tf += 1.0f) {
        float n  = __fmaf_rn(P, tf, C);
        float yf = __fmul_rn(n, nrq);
        int   ci = __float2int_rn(yf);
        float d  = yf - (float)ci;
        if (0.5f - fabsf(d) < 5e-4f) {
            ci = __float2int_rn(__fdiv_rn(-n, Q));
        }
        vals[j] = ((unsigned)ci < 256u) ? (unsigned)ci : 0xFFFFu;
    }

    unsigned prev = __shfl_up_sync(FULLM, vals[7], 1);
    if (lane == 0) prev = 0x10000u;                 // t=0 always a run start

    unsigned m = 0, vm = 0;
#pragma unroll
    for (int k = 0; k < 8; ++k) {
        if (vals[k] != prev)      m  |= 1u << k;
        if (vals[k] != 0xFFFFu)   vm |= 1u << k;
        prev = vals[k];
    }

    unsigned cnt = __popc(m & vm);
    unsigned off = cnt;
#pragma unroll
    for (int d = 1; d < 32; d <<= 1) {
        unsigned o = __shfl_up_sync(FULLM, off, d);
        if (lane >= d) off += o;
    }
    unsigned total = __shfl_sync(FULLM, off, 31);
    off -= cnt;
    if (lane == 31) { s_n[warp] = (int)total; s_mode[warp] = col ? 1u : 0u; }

    unsigned Bb = __ballot_sync(FULLM, m != 0);
    unsigned hmask = (lane == 31) ? 0u : (FULLM << (lane + 1));
    unsigned nb = Bb & hmask;
    int nl = nb ? (__ffs(nb) - 1) : lane;
    unsigned m2 = __shfl_sync(FULLM, m, nl);
    int cross_t1 = nb ? (nl * 8 + __ffs(m2) - 1) : 256;

    unsigned cur = off;
#pragma unroll
    for (int k = 0; k < 8; ++k) {
        if (((m >> k) & 1u) && ((vm >> k) & 1u)) {
            unsigned rem = m >> (k + 1);
            int t1 = rem ? (lane * 8 + k + 1 + __ffs(rem) - 1) : cross_t1;
            int t0 = lane * 8 + k;
            s_run[warp][cur++] = vals[k] | ((unsigned)t0 << 9) | ((unsigned)t1 << 18);
        }
    }

    __syncthreads();

    // ---- Phase 2: gather own pixel. lanes = pg(bits 0-1) x r(bits 2-4) ----
    const int pg = lane & 3;
    const int r  = lane >> 2;                       // 0..7 run stride
    const int n  = s_n[warp];
    const float4* __restrict__ Ptab = (s_mode[warp] ? g_tabC : g_tabR) + pg;

    float4 acc = make_float4(0.f, 0.f, 0.f, 0.f);
#pragma unroll 2
    for (int j = r; j < n; j += 8) {
        unsigned word = s_run[warp][j];
        int ci = word & 511;
        int t0 = (word >> 9) & 511;
        int t1 = word >> 18;
        float4 lo = __ldg(Ptab + (t0 * 256 + ci) * 4);
        float4 hi = __ldg(Ptab + (t1 * 256 + ci) * 4);
        acc.x += hi.x - lo.x;
        acc.y += hi.y - lo.y;
        acc.z += hi.z - lo.z;
        acc.w += hi.w - lo.w;
    }

    // Butterfly-reduce over run-stride bits (2,3,4): all lanes get pg's full sum.
    acc.x += __shfl_xor_sync(FULLM, acc.x, 4);
    acc.y += __shfl_xor_sync(FULLM, acc.y, 4);
    acc.z += __shfl_xor_sync(FULLM, acc.z, 4);
    acc.w += __shfl_xor_sync(FULLM, acc.w, 4);
    acc.x += __shfl_xor_sync(FULLM, acc.x, 8);
    acc.y += __shfl_xor_sync(FULLM, acc.y, 8);
    acc.z += __shfl_xor_sync(FULLM, acc.z, 8);
    acc.w += __shfl_xor_sync(FULLM, acc.w, 8);
    acc.x += __shfl_xor_sync(FULLM, acc.x, 16);
    acc.y += __shfl_xor_sync(FULLM, acc.y, 16);
    acc.z += __shfl_xor_sync(FULLM, acc.z, 16);
    acc.w += __shfl_xor_sync(FULLM, acc.w, 16);

    // Lanes r=0..3 store one plane each: plane = pg*4 + r, component r of acc.
    if (r < 4) {
        float vout = (r == 0) ? acc.x : (r == 1) ? acc.y : (r == 2) ? acc.z : acc.w;
        out[(pg * 4 + r) * 65536 + px] = vout;
    }
}

extern "C" void kernel_launch(void* const* d_in, const int* in_sizes, int n_in,
                              void* d_out, int out_size) {
    const float* img = (const float*)d_in[0];
    const float* F   = (const float*)d_in[1];
    if (n_in >= 2 && in_sizes[0] == 9) {            // defensive: input order swap
        img = (const float*)d_in[1];
        F   = (const float*)d_in[0];
    }
    float* out = (float*)d_out;

    transpose_k<<<1024, 256>>>(img);
    pass1_k<<<64, 256>>>();
    pass2_k<<<64, 256>>>();
    fused_k<<<8192, 256>>>(F, out);
}